// round 1
// baseline (speedup 1.0000x reference)
#include <cuda_runtime.h>
#include <math.h>

// Problem constants
#define BVAL 16
#define LVAL 4096
#define HVAL 256
#define NODES0 (BVAL * LVAL)     // 65536 leaf nodes
#define GN 1280                  // 5 gates * 256 packed output columns
#define KLVL 512                 // level GEMM K (concat of two H=256 children)

// -------- device scratch (no allocations allowed) --------
__device__ __align__(16) float g_bufA_h[(size_t)NODES0 * HVAL];          // 64 MB
__device__ __align__(16) float g_bufA_c[(size_t)NODES0 * HVAL];          // 64 MB
__device__ __align__(16) float g_bufB_h[(size_t)(NODES0 / 2) * HVAL];    // 32 MB
__device__ __align__(16) float g_bufB_c[(size_t)(NODES0 / 2) * HVAL];    // 32 MB
__device__ __align__(16) float g_G[(size_t)(NODES0 / 2) * GN];           // 168 MB gate pre-activations
__device__ __align__(16) float g_Wall[(size_t)KLVL * GN];                // packed [W_fl|W_fr|W_i|W_o|W_c]
__device__ __align__(16) float g_ball[GN];

// ---------------------------------------------------------
// Pack the 5 gate weight matrices (512x256 each) into one (512x1280),
// column blocks ordered [fl | fr | i | o | c]; same for biases.
// ---------------------------------------------------------
__global__ void pack_weights(const float* __restrict__ Wfl, const float* __restrict__ Wfr,
                             const float* __restrict__ Wi,  const float* __restrict__ Wo,
                             const float* __restrict__ Wc,
                             const float* __restrict__ bfl, const float* __restrict__ bfr,
                             const float* __restrict__ bi,  const float* __restrict__ bo,
                             const float* __restrict__ bc) {
    int idx = blockIdx.x * blockDim.x + threadIdx.x;
    int stride = gridDim.x * blockDim.x;
    const int total = KLVL * GN;
    for (int i = idx; i < total; i += stride) {
        int k = i / GN;
        int col = i - k * GN;
        int g = col >> 8;
        int j = col & 255;
        const float* W = (g == 0) ? Wfl : (g == 1) ? Wfr : (g == 2) ? Wi : (g == 3) ? Wo : Wc;
        g_Wall[i] = W[k * 256 + j];
    }
    if (idx < GN) {
        int g = idx >> 8;
        int j = idx & 255;
        const float* bb = (g == 0) ? bfl : (g == 1) ? bfr : (g == 2) ? bi : (g == 3) ? bo : bc;
        g_ball[idx] = bb[j];
    }
}

// ---------------------------------------------------------
// Leaf GEMM: H[m,:] = emb[leaf_ids[m],:] @ W_proj + b_proj ; C = tanh(H)
// M=65536, N=256, K=256. Tiled 64x64x16, 4x4 per-thread microtile.
// ---------------------------------------------------------
__global__ __launch_bounds__(256) void leaf_gemm(const int* __restrict__ ids,
                                                 const float* __restrict__ emb,
                                                 const float* __restrict__ Wp,
                                                 const float* __restrict__ bp,
                                                 float* __restrict__ Hout,
                                                 float* __restrict__ Cout) {
    const int M = NODES0, N = 256, K = 256;
    __shared__ float As[16][64];
    __shared__ float Bs[16][64];
    int tid = threadIdx.x;
    int tx = tid & 15, ty = tid >> 4;
    int rowBase = blockIdx.y * 64;
    int colBase = blockIdx.x * 64;

    float acc[4][4] = {};

    int arow = tid >> 2;
    int acol = (tid & 3) * 4;
    int gRow = rowBase + arow;
    const float* Arow = (gRow < M) ? (emb + (size_t)ids[gRow] * 256) : nullptr;

    int brow = tid >> 4;           // 0..15
    int bcol = (tid & 15) * 4;     // 0..60

    for (int kt = 0; kt < K; kt += 16) {
        float4 av = Arow ? *(const float4*)(Arow + kt + acol) : make_float4(0.f, 0.f, 0.f, 0.f);
        As[acol + 0][arow] = av.x;
        As[acol + 1][arow] = av.y;
        As[acol + 2][arow] = av.z;
        As[acol + 3][arow] = av.w;
        *(float4*)&Bs[brow][bcol] =
            *(const float4*)(Wp + (size_t)(kt + brow) * N + colBase + bcol);
        __syncthreads();
#pragma unroll
        for (int k = 0; k < 16; k++) {
            float4 a = *(const float4*)&As[k][ty * 4];
            float4 b = *(const float4*)&Bs[k][tx * 4];
            float ar[4] = {a.x, a.y, a.z, a.w};
            float br[4] = {b.x, b.y, b.z, b.w};
#pragma unroll
            for (int i = 0; i < 4; i++)
#pragma unroll
                for (int j = 0; j < 4; j++) acc[i][j] += ar[i] * br[j];
        }
        __syncthreads();
    }

#pragma unroll
    for (int i = 0; i < 4; i++) {
        int r = rowBase + ty * 4 + i;
        if (r < M) {
#pragma unroll
            for (int j = 0; j < 4; j++) {
                int cidx = colBase + tx * 4 + j;
                float h = acc[i][j] + bp[cidx];
                Hout[(size_t)r * N + cidx] = h;
                Cout[(size_t)r * N + cidx] = tanhf(h);
            }
        }
    }
}

// ---------------------------------------------------------
// Level GEMM: G[m,:] = Hin_pairs[m,:] @ W_all + b_all
// A is the previous level's H viewed as (M, 512) (siblings contiguous).
// N=1280, K=512. Same tiling.
// ---------------------------------------------------------
__global__ __launch_bounds__(256) void level_gemm(const float* __restrict__ A,
                                                  float* __restrict__ Gout, int M) {
    const int N = GN, K = KLVL;
    __shared__ float As[16][64];
    __shared__ float Bs[16][64];
    int tid = threadIdx.x;
    int tx = tid & 15, ty = tid >> 4;
    int rowBase = blockIdx.y * 64;
    int colBase = blockIdx.x * 64;

    float acc[4][4] = {};

    int arow = tid >> 2;
    int acol = (tid & 3) * 4;
    int gRow = rowBase + arow;
    const float* Arow = (gRow < M) ? (A + (size_t)gRow * K) : nullptr;

    int brow = tid >> 4;
    int bcol = (tid & 15) * 4;

    for (int kt = 0; kt < K; kt += 16) {
        float4 av = Arow ? *(const float4*)(Arow + kt + acol) : make_float4(0.f, 0.f, 0.f, 0.f);
        As[acol + 0][arow] = av.x;
        As[acol + 1][arow] = av.y;
        As[acol + 2][arow] = av.z;
        As[acol + 3][arow] = av.w;
        *(float4*)&Bs[brow][bcol] =
            *(const float4*)(g_Wall + (size_t)(kt + brow) * N + colBase + bcol);
        __syncthreads();
#pragma unroll
        for (int k = 0; k < 16; k++) {
            float4 a = *(const float4*)&As[k][ty * 4];
            float4 b = *(const float4*)&Bs[k][tx * 4];
            float ar[4] = {a.x, a.y, a.z, a.w};
            float br[4] = {b.x, b.y, b.z, b.w};
#pragma unroll
            for (int i = 0; i < 4; i++)
#pragma unroll
                for (int j = 0; j < 4; j++) acc[i][j] += ar[i] * br[j];
        }
        __syncthreads();
    }

#pragma unroll
    for (int i = 0; i < 4; i++) {
        int r = rowBase + ty * 4 + i;
        if (r < M) {
#pragma unroll
            for (int j = 0; j < 4; j++) {
                int cidx = colBase + tx * 4 + j;
                Gout[(size_t)r * N + cidx] = acc[i][j] + g_ball[cidx];
            }
        }
    }
}

// ---------------------------------------------------------
// Gate epilogue: per (node m, channel j):
//   fl,fr,ig,og = sigmoid(G[.,gate*256+j]); cc = tanh(G[.,1024+j])
//   c = fl*cl + fr*cr + ig*cc ; h = og*tanh(c)
// cl = Cin[m*512+j], cr = Cin[m*512+256+j] (siblings contiguous).
// ---------------------------------------------------------
__device__ __forceinline__ float sigmoidf_(float x) { return 1.0f / (1.0f + expf(-x)); }

__global__ __launch_bounds__(256) void gates_kernel(const float* __restrict__ G,
                                                    const float* __restrict__ Cin,
                                                    float* __restrict__ Hout,
                                                    float* __restrict__ Cout, int Mout) {
    int idx = blockIdx.x * blockDim.x + threadIdx.x;
    int total = Mout * HVAL;
    if (idx >= total) return;
    int m = idx >> 8;
    int j = idx & 255;
    const float* g = G + (size_t)m * GN;
    float fl = sigmoidf_(g[j]);
    float fr = sigmoidf_(g[256 + j]);
    float ig = sigmoidf_(g[512 + j]);
    float og = sigmoidf_(g[768 + j]);
    float cc = tanhf(g[1024 + j]);
    float cl = Cin[(size_t)m * 512 + j];
    float cr = Cin[(size_t)m * 512 + 256 + j];
    float cn = fl * cl + fr * cr + ig * cc;
    Hout[idx] = og * tanhf(cn);
    Cout[idx] = cn;
}

// ---------------------------------------------------------
// Classifier: out[b, cidx] = Hroot[b,:] @ W_cls[:, cidx] + b_cls[cidx]
// ---------------------------------------------------------
__global__ void cls_kernel(const float* __restrict__ Hroot, const float* __restrict__ Wcls,
                           const float* __restrict__ bcls, float* __restrict__ out) {
    int tid = threadIdx.x;
    if (tid >= BVAL * 2) return;
    int b = tid >> 1;
    int cidx = tid & 1;
    float sum = bcls[cidx];
    const float* h = Hroot + (size_t)b * HVAL;
    for (int k = 0; k < HVAL; k++) sum += h[k] * Wcls[k * 2 + cidx];
    out[b * 2 + cidx] = sum;
}

// ---------------------------------------------------------
extern "C" void kernel_launch(void* const* d_in, const int* in_sizes, int n_in,
                              void* d_out, int out_size) {
    const int*   leaf_ids = (const int*)d_in[0];
    const float* emb   = (const float*)d_in[1];
    const float* Wp    = (const float*)d_in[2];
    const float* bp    = (const float*)d_in[3];
    const float* Wfl   = (const float*)d_in[4];
    const float* bfl   = (const float*)d_in[5];
    const float* Wfr   = (const float*)d_in[6];
    const float* bfr   = (const float*)d_in[7];
    const float* Wi    = (const float*)d_in[8];
    const float* bi    = (const float*)d_in[9];
    const float* Wo    = (const float*)d_in[10];
    const float* bo    = (const float*)d_in[11];
    const float* Wc    = (const float*)d_in[12];
    const float* bc    = (const float*)d_in[13];
    const float* Wcls  = (const float*)d_in[14];
    const float* bcls  = (const float*)d_in[15];
    float* out = (float*)d_out;

    float *Ah, *Ac, *Bh, *Bc, *Gp;
    cudaGetSymbolAddress((void**)&Ah, g_bufA_h);
    cudaGetSymbolAddress((void**)&Ac, g_bufA_c);
    cudaGetSymbolAddress((void**)&Bh, g_bufB_h);
    cudaGetSymbolAddress((void**)&Bc, g_bufB_c);
    cudaGetSymbolAddress((void**)&Gp, g_G);

    pack_weights<<<1280, 256>>>(Wfl, Wfr, Wi, Wo, Wc, bfl, bfr, bi, bo, bc);

    // Leaf level: M=65536, N=256 -> grid (4, 1024)
    leaf_gemm<<<dim3(256 / 64, NODES0 / 64), 256>>>(leaf_ids, emb, Wp, bp, Ah, Ac);

    float *inH = Ah, *inC = Ac, *outH = Bh, *outC = Bc;
    int cur = NODES0;
    while (cur > BVAL) {
        int Mout = cur >> 1;
        dim3 grid(GN / 64, (Mout + 63) / 64);
        level_gemm<<<grid, 256>>>(inH, Gp, Mout);
        int tot = Mout * HVAL;
        gates_kernel<<<(tot + 255) / 256, 256>>>(Gp, inC, outH, outC, Mout);
        float* t;
        t = inH; inH = outH; outH = t;
        t = inC; inC = outC; outC = t;
        cur = Mout;
    }

    cls_kernel<<<1, 32>>>(inH, Wcls, bcls, out);
}

// round 4
// speedup vs baseline: 2.7244x; 2.7244x over previous
#include <cuda_runtime.h>
#include <cstdint>
#include <math.h>

#define BVAL 16
#define HVAL 256
#define NODES0 65536

// ---------------- device scratch ----------------
__device__ __align__(16) float g_bufA_h[(size_t)NODES0 * HVAL];
__device__ __align__(16) float g_bufA_c[(size_t)NODES0 * HVAL];
__device__ __align__(16) float g_bufB_h[(size_t)(NODES0 / 2) * HVAL];
__device__ __align__(16) float g_bufB_c[(size_t)(NODES0 / 2) * HVAL];
__device__ __align__(16) float g_Wk[(size_t)512 * 1280];    // gate weights k-major [k][p], p=grp*160+g*32+jj, tf32-RN
__device__ __align__(16) float g_WpK[(size_t)256 * 256];    // W_proj [k][n], tf32-RN
__device__ __align__(16) float g_embR[(size_t)50000 * 256]; // emb rounded to tf32-RN
__device__ __align__(16) float g_bt[1280];                  // packed gate biases (same p order)

// ---------------- helpers ----------------
__device__ __forceinline__ float rnd_tf32(float x) {
    uint32_t r;
    asm("cvt.rna.tf32.f32 %0, %1;" : "=r"(r) : "f"(x));
    return __uint_as_float(r);
}
__device__ __forceinline__ float sigm(float x) { return 1.0f / (1.0f + __expf(-x)); }

__device__ __forceinline__ void cp16(void* dst, const float* src) {
    uint32_t d = (uint32_t)__cvta_generic_to_shared(dst);
    asm volatile("cp.async.cg.shared.global [%0], [%1], 16;"
                 :: "r"(d), "l"(__cvta_generic_to_global(src)));
}
#define CP_COMMIT() asm volatile("cp.async.commit_group;" ::: "memory")
#define CP_WAIT1()  asm volatile("cp.async.wait_group 1;" ::: "memory")
#define CP_WAIT0()  asm volatile("cp.async.wait_group 0;" ::: "memory")

__device__ __forceinline__ void mma_tf32(float* c, const uint32_t* a, uint32_t b0, uint32_t b1) {
    asm volatile("mma.sync.aligned.m16n8k8.row.col.f32.tf32.tf32.f32 "
                 "{%0,%1,%2,%3}, {%4,%5,%6,%7}, {%8,%9}, {%0,%1,%2,%3};"
                 : "+f"(c[0]), "+f"(c[1]), "+f"(c[2]), "+f"(c[3])
                 : "r"(a[0]), "r"(a[1]), "r"(a[2]), "r"(a[3]), "r"(b0), "r"(b1));
}

// ---------------- pack kernel: transpose/pack weights + round everything to tf32-RN ----------------
__global__ void pack_weights(const float* __restrict__ emb, const float* __restrict__ Wp,
                             const float* __restrict__ Wfl, const float* __restrict__ Wfr,
                             const float* __restrict__ Wi,  const float* __restrict__ Wo,
                             const float* __restrict__ Wc,
                             const float* __restrict__ bfl, const float* __restrict__ bfr,
                             const float* __restrict__ bi,  const float* __restrict__ bo,
                             const float* __restrict__ bc) {
    int idx = blockIdx.x * blockDim.x + threadIdx.x;
    int stride = gridDim.x * blockDim.x;
    // gate weights: g_Wk[k][p], p = grp*160 + g*32 + jj  -> W_g[k][grp*32+jj]
    for (int i = idx; i < 512 * 1280; i += stride) {
        int k = i / 1280, p = i - k * 1280;
        int grp = p / 160, rem = p - grp * 160;
        int g = rem >> 5, jj = rem & 31;
        const float* W = (g == 0) ? Wfl : (g == 1) ? Wfr : (g == 2) ? Wi : (g == 3) ? Wo : Wc;
        g_Wk[i] = rnd_tf32(W[k * 256 + grp * 32 + jj]);
    }
    for (int i = idx; i < 256 * 256; i += stride) g_WpK[i] = rnd_tf32(Wp[i]);
    for (size_t i = idx; i < (size_t)50000 * 256; i += stride) g_embR[i] = rnd_tf32(emb[i]);
    for (int i = idx; i < 1280; i += stride) {
        int grp = i / 160, rem = i - grp * 160;
        int g = rem >> 5, jj = rem & 31;
        const float* bb = (g == 0) ? bfl : (g == 1) ? bfr : (g == 2) ? bi : (g == 3) ? bo : bc;
        g_bt[i] = bb[grp * 32 + jj];
    }
}

// ================= LEVEL KERNEL (fused tf32 mma GEMM + gates) =================
// CTA tile: M=128, N=160 (=32 channels x 5 gates), K=512, k-chunk 32, 2-stage cp.async.
// Warps: 4 along M (32 rows each) x 2 along channels (16 each).
#define LV_AF 4608              // 128 * 36 floats per A stage
#define LV_BF 5376              // 32 * 168 floats per B stage
#define LV_STGF (LV_AF + LV_BF)
#define LV_SMEM (2 * LV_STGF * 4)
#define ASTR 36
#define BSTR 168

__global__ __launch_bounds__(256, 1) void level_fused(const float* __restrict__ Hin,
                                                      const float* __restrict__ Cin,
                                                      float* __restrict__ Hout,
                                                      float* __restrict__ Cout, int Mout) {
    extern __shared__ float dsm[];
    __shared__ float s_bias[160];
    const int tid = threadIdx.x, wid = tid >> 5, lane = tid & 31;
    const int qr = lane >> 2, qc = lane & 3;
    const int wm = wid >> 1, wn = wid & 1;
    const int mBase = blockIdx.x * 128;
    const int grp = blockIdx.y;
    const int p0 = grp * 160, c0 = grp * 32;

    for (int i = tid; i < 160; i += 256) s_bias[i] = g_bt[p0 + i];

    float acc[2][10][4];
#pragma unroll
    for (int a = 0; a < 2; a++)
#pragma unroll
        for (int b = 0; b < 10; b++)
#pragma unroll
            for (int e = 0; e < 4; e++) acc[a][b][e] = 0.f;

    auto load_chunk = [&](int kc) {
        float* As = dsm + (kc & 1) * LV_STGF;
        float* Bs = As + LV_AF;
#pragma unroll
        for (int t = 0; t < 4; t++) {
            int v = tid + t * 256;
            int r = v >> 3, c = v & 7;
            int row = mBase + r; if (row >= Mout) row = Mout - 1;
            cp16(As + r * ASTR + c * 4, Hin + (size_t)row * 512 + kc * 32 + c * 4);
        }
#pragma unroll
        for (int t = 0; t < 5; t++) {
            int v = tid + t * 256;
            int kr = v / 40, c4 = v - kr * 40;
            cp16(Bs + kr * BSTR + c4 * 4, g_Wk + (size_t)(kc * 32 + kr) * 1280 + p0 + c4 * 4);
        }
        CP_COMMIT();
    };

    load_chunk(0);
    for (int i = 0; i < 16; i++) {
        if (i + 1 < 16) { load_chunk(i + 1); CP_WAIT1(); } else { CP_WAIT0(); }
        __syncthreads();
        const float* As = dsm + (i & 1) * LV_STGF;
        const float* Bs = As + LV_AF;
#pragma unroll
        for (int ks = 0; ks < 4; ks++) {
            uint32_t a[2][4];
#pragma unroll
            for (int ma = 0; ma < 2; ma++) {
                const float* ap = As + (wm * 32 + ma * 16 + qr) * ASTR + ks * 8 + qc;
                a[ma][0] = __float_as_uint(ap[0]);
                a[ma][1] = __float_as_uint(ap[8 * ASTR]);
                a[ma][2] = __float_as_uint(ap[4]);
                a[ma][3] = __float_as_uint(ap[8 * ASTR + 4]);
            }
#pragma unroll
            for (int na = 0; na < 10; na++) {
                int col = (na >> 1) * 32 + wn * 16 + (na & 1) * 8 + qr;
                const float* bp = Bs + (ks * 8 + qc) * BSTR + col;
                uint32_t b0 = __float_as_uint(bp[0]);
                uint32_t b1 = __float_as_uint(bp[4 * BSTR]);
                mma_tf32(acc[0][na], a[0], b0, b1);
                mma_tf32(acc[1][na], a[1], b0, b1);
            }
        }
        __syncthreads();
    }

    // fused gate epilogue from register accumulators
#pragma unroll
    for (int ma = 0; ma < 2; ma++) {
#pragma unroll
        for (int eh = 0; eh < 2; eh++) {  // row half within m16 atom
            int row = mBase + wm * 32 + ma * 16 + qr + eh * 8;
            if (row < Mout) {
#pragma unroll
                for (int na = 0; na < 2; na++) {
                    int jj = wn * 16 + na * 8 + qc * 2;  // channel pair base (local)
                    float2 cl = *(const float2*)(Cin + (size_t)row * 512 + c0 + jj);
                    float2 cr = *(const float2*)(Cin + (size_t)row * 512 + 256 + c0 + jj);
                    float hv[2], cv[2];
#pragma unroll
                    for (int e = 0; e < 2; e++) {
                        int bi_ = jj + e;
                        float fl = sigm(acc[ma][0 * 2 + na][eh * 2 + e] + s_bias[0 * 32 + bi_]);
                        float fr = sigm(acc[ma][1 * 2 + na][eh * 2 + e] + s_bias[1 * 32 + bi_]);
                        float ig = sigm(acc[ma][2 * 2 + na][eh * 2 + e] + s_bias[2 * 32 + bi_]);
                        float og = sigm(acc[ma][3 * 2 + na][eh * 2 + e] + s_bias[3 * 32 + bi_]);
                        float cc = tanhf(acc[ma][4 * 2 + na][eh * 2 + e] + s_bias[4 * 32 + bi_]);
                        float clv = (e == 0) ? cl.x : cl.y;
                        float crv = (e == 0) ? cr.x : cr.y;
                        float cn = fl * clv + fr * crv + ig * cc;
                        cv[e] = cn;
                        hv[e] = rnd_tf32(og * tanhf(cn));
                    }
                    *(float2*)(Hout + (size_t)row * 256 + c0 + jj) = make_float2(hv[0], hv[1]);
                    *(float2*)(Cout + (size_t)row * 256 + c0 + jj) = make_float2(cv[0], cv[1]);
                }
            }
        }
    }
}

// ================= LEAF KERNEL (fused gather tf32 mma GEMM + tanh) =================
// CTA tile: M=128, N=128, K=256, k-chunk 32. Warps 4x2 (warp 32x64).
#define LF_AF 4608              // 128 * 36
#define LF_BF 4352              // 32 * 136
#define LF_STGF (LF_AF + LF_BF)
#define LF_SMEM (2 * LF_STGF * 4)
#define BSTRL 136

__global__ __launch_bounds__(256, 1) void leaf_fused(const int* __restrict__ ids,
                                                     const float* __restrict__ bp,
                                                     float* __restrict__ Hout,
                                                     float* __restrict__ Cout) {
    extern __shared__ float dsm[];
    __shared__ int s_ids[128];
    __shared__ float s_bp[128];
    const int tid = threadIdx.x, wid = tid >> 5, lane = tid & 31;
    const int qr = lane >> 2, qc = lane & 3;
    const int wm = wid >> 1, wn = wid & 1;
    const int mBase = blockIdx.x * 128;
    const int nBase = blockIdx.y * 128;

    if (tid < 128) {
        s_ids[tid] = ids[mBase + tid];
        s_bp[tid] = bp[nBase + tid];
    }
    __syncthreads();

    float acc[2][8][4];
#pragma unroll
    for (int a = 0; a < 2; a++)
#pragma unroll
        for (int b = 0; b < 8; b++)
#pragma unroll
            for (int e = 0; e < 4; e++) acc[a][b][e] = 0.f;

    auto load_chunk = [&](int kc) {
        float* As = dsm + (kc & 1) * LF_STGF;
        float* Bs = As + LF_AF;
#pragma unroll
        for (int t = 0; t < 4; t++) {
            int v = tid + t * 256;
            int r = v >> 3, c = v & 7;
            cp16(As + r * ASTR + c * 4, g_embR + (size_t)s_ids[r] * 256 + kc * 32 + c * 4);
        }
#pragma unroll
        for (int t = 0; t < 4; t++) {
            int v = tid + t * 256;
            int kr = v >> 5, c4 = v & 31;
            cp16(Bs + kr * BSTRL + c4 * 4, g_WpK + (size_t)(kc * 32 + kr) * 256 + nBase + c4 * 4);
        }
        CP_COMMIT();
    };

    load_chunk(0);
    for (int i = 0; i < 8; i++) {
        if (i + 1 < 8) { load_chunk(i + 1); CP_WAIT1(); } else { CP_WAIT0(); }
        __syncthreads();
        const float* As = dsm + (i & 1) * LF_STGF;
        const float* Bs = As + LF_AF;
#pragma unroll
        for (int ks = 0; ks < 4; ks++) {
            uint32_t a[2][4];
#pragma unroll
            for (int ma = 0; ma < 2; ma++) {
                const float* ap = As + (wm * 32 + ma * 16 + qr) * ASTR + ks * 8 + qc;
                a[ma][0] = __float_as_uint(ap[0]);
                a[ma][1] = __float_as_uint(ap[8 * ASTR]);
                a[ma][2] = __float_as_uint(ap[4]);
                a[ma][3] = __float_as_uint(ap[8 * ASTR + 4]);
            }
#pragma unroll
            for (int na = 0; na < 8; na++) {
                int col = wn * 64 + na * 8 + qr;
                const float* bpS = Bs + (ks * 8 + qc) * BSTRL + col;
                uint32_t b0 = __float_as_uint(bpS[0]);
                uint32_t b1 = __float_as_uint(bpS[4 * BSTRL]);
                mma_tf32(acc[0][na], a[0], b0, b1);
                mma_tf32(acc[1][na], a[1], b0, b1);
            }
        }
        __syncthreads();
    }

#pragma unroll
    for (int ma = 0; ma < 2; ma++) {
#pragma unroll
        for (int eh = 0; eh < 2; eh++) {
            int row = mBase + wm * 32 + ma * 16 + qr + eh * 8;
#pragma unroll
            for (int na = 0; na < 8; na++) {
                int cl = wn * 64 + na * 8 + qc * 2;  // local col pair
                float h0 = acc[ma][na][eh * 2 + 0] + s_bp[cl + 0];
                float h1 = acc[ma][na][eh * 2 + 1] + s_bp[cl + 1];
                *(float2*)(Hout + (size_t)row * 256 + nBase + cl) =
                    make_float2(rnd_tf32(h0), rnd_tf32(h1));
                *(float2*)(Cout + (size_t)row * 256 + nBase + cl) =
                    make_float2(tanhf(h0), tanhf(h1));
            }
        }
    }
}

// ---------------- classifier ----------------
__global__ void cls_kernel(const float* __restrict__ Hroot, const float* __restrict__ Wcls,
                           const float* __restrict__ bcls, float* __restrict__ out) {
    int tid = threadIdx.x;
    if (tid >= BVAL * 2) return;
    int b = tid >> 1;
    int cidx = tid & 1;
    float sum = bcls[cidx];
    const float* h = Hroot + (size_t)b * HVAL;
    for (int k = 0; k < HVAL; k++) sum += h[k] * Wcls[k * 2 + cidx];
    out[b * 2 + cidx] = sum;
}

// ---------------- launch ----------------
extern "C" void kernel_launch(void* const* d_in, const int* in_sizes, int n_in,
                              void* d_out, int out_size) {
    const int*   leaf_ids = (const int*)d_in[0];
    const float* emb  = (const float*)d_in[1];
    const float* Wp   = (const float*)d_in[2];
    const float* bp   = (const float*)d_in[3];
    const float* Wfl  = (const float*)d_in[4];
    const float* bfl  = (const float*)d_in[5];
    const float* Wfr  = (const float*)d_in[6];
    const float* bfr  = (const float*)d_in[7];
    const float* Wi   = (const float*)d_in[8];
    const float* bi   = (const float*)d_in[9];
    const float* Wo   = (const float*)d_in[10];
    const float* bo   = (const float*)d_in[11];
    const float* Wc   = (const float*)d_in[12];
    const float* bc   = (const float*)d_in[13];
    const float* Wcls = (const float*)d_in[14];
    const float* bcls = (const float*)d_in[15];
    float* out = (float*)d_out;

    float *Ah, *Ac, *Bh, *Bc;
    cudaGetSymbolAddress((void**)&Ah, g_bufA_h);
    cudaGetSymbolAddress((void**)&Ac, g_bufA_c);
    cudaGetSymbolAddress((void**)&Bh, g_bufB_h);
    cudaGetSymbolAddress((void**)&Bc, g_bufB_c);

    cudaFuncSetAttribute(level_fused, cudaFuncAttributeMaxDynamicSharedMemorySize, LV_SMEM);
    cudaFuncSetAttribute(leaf_fused,  cudaFuncAttributeMaxDynamicSharedMemorySize, LF_SMEM);

    pack_weights<<<512, 256>>>(emb, Wp, Wfl, Wfr, Wi, Wo, Wc, bfl, bfr, bi, bo, bc);

    leaf_fused<<<dim3(NODES0 / 128, 2), 256, LF_SMEM>>>(leaf_ids, bp, Ah, Ac);

    float *inH = Ah, *inC = Ac, *outH = Bh, *outC = Bc;
    int cur = NODES0;
    while (cur > BVAL) {
        int Mout = cur >> 1;
        dim3 grid((Mout + 127) / 128, 8);
        level_fused<<<grid, 256, LV_SMEM>>>(inH, inC, outH, outC, Mout);
        float* t;
        t = inH; inH = outH; outH = t;
        t = inC; inC = outC; outC = t;
        cur = Mout;
    }

    cls_kernel<<<1, 32>>>(inH, Wcls, bcls, out);
}

// round 5
// speedup vs baseline: 3.7288x; 1.3687x over previous
#include <cuda_runtime.h>
#include <cstdint>
#include <math.h>

#define BVAL 16
#define HVAL 256
#define NODES0 65536

// ---------------- device scratch ----------------
__device__ __align__(16) float g_bufA_h[(size_t)NODES0 * HVAL];
__device__ __align__(16) float g_bufA_c[(size_t)NODES0 * HVAL];
__device__ __align__(16) float g_bufB_h[(size_t)(NODES0 / 2) * HVAL];
__device__ __align__(16) float g_bufB_c[(size_t)(NODES0 / 2) * HVAL];
__device__ __align__(16) float g_Wk[(size_t)512 * 1280];    // gate weights k-major [k][p], p=grp*160+g*32+jj
__device__ __align__(16) float g_WpK[(size_t)256 * 256];    // W_proj [k][n], tf32-RN
__device__ __align__(16) float g_embR[(size_t)50000 * 256]; // emb rounded to tf32-RN
__device__ __align__(16) float g_bt[1280];                  // packed gate biases

__device__ unsigned g_bar_cnt = 0;
__device__ unsigned g_bar_gen = 0;

// ---------------- helpers ----------------
__device__ __forceinline__ float rnd_tf32(float x) {
    uint32_t r;
    asm("cvt.rna.tf32.f32 %0, %1;" : "=r"(r) : "f"(x));
    return __uint_as_float(r);
}
__device__ __forceinline__ float sigm(float x) { return 1.0f / (1.0f + __expf(-x)); }

__device__ __forceinline__ void cp16(void* dst, const float* src) {
    uint32_t d = (uint32_t)__cvta_generic_to_shared(dst);
    asm volatile("cp.async.cg.shared.global [%0], [%1], 16;"
                 :: "r"(d), "l"(__cvta_generic_to_global(src)));
}
#define CP_COMMIT() asm volatile("cp.async.commit_group;" ::: "memory")
#define CP_WAIT1()  asm volatile("cp.async.wait_group 1;" ::: "memory")
#define CP_WAIT0()  asm volatile("cp.async.wait_group 0;" ::: "memory")

__device__ __forceinline__ void mma_tf32(float* c, const uint32_t* a, uint32_t b0, uint32_t b1) {
    asm volatile("mma.sync.aligned.m16n8k8.row.col.f32.tf32.tf32.f32 "
                 "{%0,%1,%2,%3}, {%4,%5,%6,%7}, {%8,%9}, {%0,%1,%2,%3};"
                 : "+f"(c[0]), "+f"(c[1]), "+f"(c[2]), "+f"(c[3])
                 : "r"(a[0]), "r"(a[1]), "r"(a[2]), "r"(a[3]), "r"(b0), "r"(b1));
}

// ---------------- pack kernel ----------------
__global__ void pack_weights(const float* __restrict__ emb, const float* __restrict__ Wp,
                             const float* __restrict__ Wfl, const float* __restrict__ Wfr,
                             const float* __restrict__ Wi,  const float* __restrict__ Wo,
                             const float* __restrict__ Wc,
                             const float* __restrict__ bfl, const float* __restrict__ bfr,
                             const float* __restrict__ bi,  const float* __restrict__ bo,
                             const float* __restrict__ bc) {
    int idx = blockIdx.x * blockDim.x + threadIdx.x;
    int stride = gridDim.x * blockDim.x;
    for (int i = idx; i < 512 * 1280; i += stride) {
        int k = i / 1280, p = i - k * 1280;
        int grp = p / 160, rem = p - grp * 160;
        int g = rem >> 5, jj = rem & 31;
        const float* W = (g == 0) ? Wfl : (g == 1) ? Wfr : (g == 2) ? Wi : (g == 3) ? Wo : Wc;
        g_Wk[i] = rnd_tf32(W[k * 256 + grp * 32 + jj]);
    }
    for (int i = idx; i < 256 * 256; i += stride) g_WpK[i] = rnd_tf32(Wp[i]);
    for (size_t i = idx; i < (size_t)50000 * 256; i += stride) g_embR[i] = rnd_tf32(emb[i]);
    for (int i = idx; i < 1280; i += stride) {
        int grp = i / 160, rem = i - grp * 160;
        int g = rem >> 5, jj = rem & 31;
        const float* bb = (g == 0) ? bfl : (g == 1) ? bfr : (g == 2) ? bi : (g == 3) ? bo : bc;
        g_bt[i] = bb[grp * 32 + jj];
    }
}

// ================= LEVEL KERNEL (big levels) =================
#define LV_AF 4608
#define LV_BF 5376
#define LV_STGF (LV_AF + LV_BF)
#define LV_SMEM (2 * LV_STGF * 4)
#define ASTR 36
#define BSTR 168

__global__ __launch_bounds__(256, 2) void level_fused(const float* __restrict__ Hin,
                                                      const float* __restrict__ Cin,
                                                      float* __restrict__ Hout,
                                                      float* __restrict__ Cout, int Mout) {
    extern __shared__ float dsm[];
    __shared__ float s_bias[160];
    const int tid = threadIdx.x, wid = tid >> 5, lane = tid & 31;
    const int qr = lane >> 2, qc = lane & 3;
    const int wm = wid >> 1, wn = wid & 1;
    const int mBase = blockIdx.x * 128;
    const int grp = blockIdx.y;
    const int p0 = grp * 160, c0 = grp * 32;

    for (int i = tid; i < 160; i += 256) s_bias[i] = g_bt[p0 + i];

    float acc[2][10][4];
#pragma unroll
    for (int a = 0; a < 2; a++)
#pragma unroll
        for (int b = 0; b < 10; b++)
#pragma unroll
            for (int e = 0; e < 4; e++) acc[a][b][e] = 0.f;

    auto load_chunk = [&](int kc) {
        float* As = dsm + (kc & 1) * LV_STGF;
        float* Bs = As + LV_AF;
#pragma unroll
        for (int t = 0; t < 4; t++) {
            int v = tid + t * 256;
            int r = v >> 3, c = v & 7;
            int row = mBase + r; if (row >= Mout) row = Mout - 1;
            cp16(As + r * ASTR + c * 4, Hin + (size_t)row * 512 + kc * 32 + c * 4);
        }
#pragma unroll
        for (int t = 0; t < 5; t++) {
            int v = tid + t * 256;
            int kr = v / 40, c4 = v - kr * 40;
            cp16(Bs + kr * BSTR + c4 * 4, g_Wk + (size_t)(kc * 32 + kr) * 1280 + p0 + c4 * 4);
        }
        CP_COMMIT();
    };

    load_chunk(0);
    for (int i = 0; i < 16; i++) {
        if (i + 1 < 16) { load_chunk(i + 1); CP_WAIT1(); } else { CP_WAIT0(); }
        __syncthreads();
        const float* As = dsm + (i & 1) * LV_STGF;
        const float* Bs = As + LV_AF;
#pragma unroll
        for (int ks = 0; ks < 4; ks++) {
            uint32_t a[2][4];
#pragma unroll
            for (int ma = 0; ma < 2; ma++) {
                const float* ap = As + (wm * 32 + ma * 16 + qr) * ASTR + ks * 8 + qc;
                a[ma][0] = __float_as_uint(ap[0]);
                a[ma][1] = __float_as_uint(ap[8 * ASTR]);
                a[ma][2] = __float_as_uint(ap[4]);
                a[ma][3] = __float_as_uint(ap[8 * ASTR + 4]);
            }
#pragma unroll
            for (int na = 0; na < 10; na++) {
                int col = (na >> 1) * 32 + wn * 16 + (na & 1) * 8 + qr;
                const float* bp = Bs + (ks * 8 + qc) * BSTR + col;
                uint32_t b0 = __float_as_uint(bp[0]);
                uint32_t b1 = __float_as_uint(bp[4 * BSTR]);
                mma_tf32(acc[0][na], a[0], b0, b1);
                mma_tf32(acc[1][na], a[1], b0, b1);
            }
        }
        __syncthreads();
    }

#pragma unroll
    for (int ma = 0; ma < 2; ma++) {
#pragma unroll
        for (int eh = 0; eh < 2; eh++) {
            int row = mBase + wm * 32 + ma * 16 + qr + eh * 8;
            if (row < Mout) {
#pragma unroll
                for (int na = 0; na < 2; na++) {
                    int jj = wn * 16 + na * 8 + qc * 2;
                    float2 cl = *(const float2*)(Cin + (size_t)row * 512 + c0 + jj);
                    float2 cr = *(const float2*)(Cin + (size_t)row * 512 + 256 + c0 + jj);
                    float hv[2], cv[2];
#pragma unroll
                    for (int e = 0; e < 2; e++) {
                        int bi_ = jj + e;
                        float fl = sigm(acc[ma][0 * 2 + na][eh * 2 + e] + s_bias[0 * 32 + bi_]);
                        float fr = sigm(acc[ma][1 * 2 + na][eh * 2 + e] + s_bias[1 * 32 + bi_]);
                        float ig = sigm(acc[ma][2 * 2 + na][eh * 2 + e] + s_bias[2 * 32 + bi_]);
                        float og = sigm(acc[ma][3 * 2 + na][eh * 2 + e] + s_bias[3 * 32 + bi_]);
                        float cc = tanhf(acc[ma][4 * 2 + na][eh * 2 + e] + s_bias[4 * 32 + bi_]);
                        float clv = (e == 0) ? cl.x : cl.y;
                        float crv = (e == 0) ? cr.x : cr.y;
                        float cn = fl * clv + fr * crv + ig * cc;
                        cv[e] = cn;
                        hv[e] = rnd_tf32(og * tanhf(cn));
                    }
                    *(float2*)(Hout + (size_t)row * 256 + c0 + jj) = make_float2(hv[0], hv[1]);
                    *(float2*)(Cout + (size_t)row * 256 + c0 + jj) = make_float2(cv[0], cv[1]);
                }
            }
        }
    }
}

// ================= LEAF KERNEL =================
#define LF_AF 4608
#define LF_BF 4352
#define LF_STGF (LF_AF + LF_BF)
#define LF_SMEM (2 * LF_STGF * 4)
#define BSTRL 136

__global__ __launch_bounds__(256, 2) void leaf_fused(const int* __restrict__ ids,
                                                     const float* __restrict__ bp,
                                                     float* __restrict__ Hout,
                                                     float* __restrict__ Cout) {
    extern __shared__ float dsm[];
    __shared__ int s_ids[128];
    __shared__ float s_bp[128];
    const int tid = threadIdx.x, wid = tid >> 5, lane = tid & 31;
    const int qr = lane >> 2, qc = lane & 3;
    const int wm = wid >> 1, wn = wid & 1;
    const int mBase = blockIdx.x * 128;
    const int nBase = blockIdx.y * 128;

    if (tid < 128) {
        s_ids[tid] = ids[mBase + tid];
        s_bp[tid] = bp[nBase + tid];
    }
    __syncthreads();

    float acc[2][8][4];
#pragma unroll
    for (int a = 0; a < 2; a++)
#pragma unroll
        for (int b = 0; b < 8; b++)
#pragma unroll
            for (int e = 0; e < 4; e++) acc[a][b][e] = 0.f;

    auto load_chunk = [&](int kc) {
        float* As = dsm + (kc & 1) * LF_STGF;
        float* Bs = As + LF_AF;
#pragma unroll
        for (int t = 0; t < 4; t++) {
            int v = tid + t * 256;
            int r = v >> 3, c = v & 7;
            cp16(As + r * ASTR + c * 4, g_embR + (size_t)s_ids[r] * 256 + kc * 32 + c * 4);
        }
#pragma unroll
        for (int t = 0; t < 4; t++) {
            int v = tid + t * 256;
            int kr = v >> 5, c4 = v & 31;
            cp16(Bs + kr * BSTRL + c4 * 4, g_WpK + (size_t)(kc * 32 + kr) * 256 + nBase + c4 * 4);
        }
        CP_COMMIT();
    };

    load_chunk(0);
    for (int i = 0; i < 8; i++) {
        if (i + 1 < 8) { load_chunk(i + 1); CP_WAIT1(); } else { CP_WAIT0(); }
        __syncthreads();
        const float* As = dsm + (i & 1) * LF_STGF;
        const float* Bs = As + LF_AF;
#pragma unroll
        for (int ks = 0; ks < 4; ks++) {
            uint32_t a[2][4];
#pragma unroll
            for (int ma = 0; ma < 2; ma++) {
                const float* ap = As + (wm * 32 + ma * 16 + qr) * ASTR + ks * 8 + qc;
                a[ma][0] = __float_as_uint(ap[0]);
                a[ma][1] = __float_as_uint(ap[8 * ASTR]);
                a[ma][2] = __float_as_uint(ap[4]);
                a[ma][3] = __float_as_uint(ap[8 * ASTR + 4]);
            }
#pragma unroll
            for (int na = 0; na < 8; na++) {
                int col = wn * 64 + na * 8 + qr;
                const float* bpS = Bs + (ks * 8 + qc) * BSTRL + col;
                uint32_t b0 = __float_as_uint(bpS[0]);
                uint32_t b1 = __float_as_uint(bpS[4 * BSTRL]);
                mma_tf32(acc[0][na], a[0], b0, b1);
                mma_tf32(acc[1][na], a[1], b0, b1);
            }
        }
        __syncthreads();
    }

#pragma unroll
    for (int ma = 0; ma < 2; ma++) {
#pragma unroll
        for (int eh = 0; eh < 2; eh++) {
            int row = mBase + wm * 32 + ma * 16 + qr + eh * 8;
#pragma unroll
            for (int na = 0; na < 8; na++) {
                int cl = wn * 64 + na * 8 + qc * 2;
                float h0 = acc[ma][na][eh * 2 + 0] + s_bp[cl + 0];
                float h1 = acc[ma][na][eh * 2 + 1] + s_bp[cl + 1];
                *(float2*)(Hout + (size_t)row * 256 + nBase + cl) =
                    make_float2(rnd_tf32(h0), rnd_tf32(h1));
                *(float2*)(Cout + (size_t)row * 256 + nBase + cl) =
                    make_float2(tanhf(h0), tanhf(h1));
            }
        }
    }
}

// ================= PERSISTENT SMALL-LEVELS KERNEL =================
// Handles cur=4096 -> root (8 levels) + classifier, one launch, grid barrier between levels.
// Tile: M=64 x Ngrp=160 (32 channels x 5 gates). Warps 4(M) x 2(N). acc[10][4].
#define SL_GRID 128
#define SL_AF 2304              // 64 * 36
#define SL_BF 5376              // 32 * 168
#define SL_STGF (SL_AF + SL_BF)
#define SL_SMEM (2 * SL_STGF * 4)

__global__ __launch_bounds__(256, 1) void small_levels(float* __restrict__ inH0,
                                                       float* __restrict__ inC0,
                                                       float* __restrict__ outH0,
                                                       float* __restrict__ outC0,
                                                       const float* __restrict__ Wcls,
                                                       const float* __restrict__ bcls,
                                                       float* __restrict__ out) {
    extern __shared__ float dsm[];
    __shared__ float s_bias[160];
    const int tid = threadIdx.x, wid = tid >> 5, lane = tid & 31;
    const int qr = lane >> 2, qc = lane & 3;
    const int wm = wid >> 1, wn = wid & 1;

    unsigned gen = 0;
    if (tid == 0) gen = *(volatile unsigned*)&g_bar_gen;

    float* inH = inH0;  float* inC = inC0;
    float* outH = outH0; float* outC = outC0;

    int cur = 4096;
    while (cur > 16) {
        const int Mout = cur >> 1;
        const int mtiles = (Mout + 63) >> 6;
        const int nt = mtiles * 8;
        for (int t = blockIdx.x; t < nt; t += SL_GRID) {
            const int grp = t / mtiles;
            const int mtile = t - grp * mtiles;
            const int p0 = grp * 160, c0 = grp * 32;
            const int mBase = mtile * 64;

            for (int i = tid; i < 160; i += 256) s_bias[i] = g_bt[p0 + i];

            float acc[10][4];
#pragma unroll
            for (int b = 0; b < 10; b++)
#pragma unroll
                for (int e = 0; e < 4; e++) acc[b][e] = 0.f;

            auto load_chunk = [&](int kc) {
                float* As = dsm + (kc & 1) * SL_STGF;
                float* Bs = As + SL_AF;
#pragma unroll
                for (int tt = 0; tt < 2; tt++) {
                    int v = tid + tt * 256;
                    int r = v >> 3, c = v & 7;
                    int row = mBase + r; if (row >= Mout) row = Mout - 1;
                    cp16(As + r * ASTR + c * 4, inH + (size_t)row * 512 + kc * 32 + c * 4);
                }
#pragma unroll
                for (int tt = 0; tt < 5; tt++) {
                    int v = tid + tt * 256;
                    int kr = v / 40, c4 = v - kr * 40;
                    cp16(Bs + kr * BSTR + c4 * 4, g_Wk + (size_t)(kc * 32 + kr) * 1280 + p0 + c4 * 4);
                }
                CP_COMMIT();
            };

            load_chunk(0);
            for (int i = 0; i < 16; i++) {
                if (i + 1 < 16) { load_chunk(i + 1); CP_WAIT1(); } else { CP_WAIT0(); }
                __syncthreads();
                const float* As = dsm + (i & 1) * SL_STGF;
                const float* Bs = As + SL_AF;
#pragma unroll
                for (int ks = 0; ks < 4; ks++) {
                    uint32_t a[4];
                    const float* ap = As + (wm * 16 + qr) * ASTR + ks * 8 + qc;
                    a[0] = __float_as_uint(ap[0]);
                    a[1] = __float_as_uint(ap[8 * ASTR]);
                    a[2] = __float_as_uint(ap[4]);
                    a[3] = __float_as_uint(ap[8 * ASTR + 4]);
#pragma unroll
                    for (int na = 0; na < 10; na++) {
                        int col = (na >> 1) * 32 + wn * 16 + (na & 1) * 8 + qr;
                        const float* bp = Bs + (ks * 8 + qc) * BSTR + col;
                        mma_tf32(acc[na], a, __float_as_uint(bp[0]), __float_as_uint(bp[4 * BSTR]));
                    }
                }
                __syncthreads();
            }

#pragma unroll
            for (int eh = 0; eh < 2; eh++) {
                int row = mBase + wm * 16 + qr + eh * 8;
                if (row < Mout) {
#pragma unroll
                    for (int na = 0; na < 2; na++) {
                        int jj = wn * 16 + na * 8 + qc * 2;
                        float2 cl = *(const float2*)(inC + (size_t)row * 512 + c0 + jj);
                        float2 cr = *(const float2*)(inC + (size_t)row * 512 + 256 + c0 + jj);
                        float hv[2], cv[2];
#pragma unroll
                        for (int e = 0; e < 2; e++) {
                            int bi_ = jj + e;
                            float fl = sigm(acc[0 * 2 + na][eh * 2 + e] + s_bias[0 * 32 + bi_]);
                            float fr = sigm(acc[1 * 2 + na][eh * 2 + e] + s_bias[1 * 32 + bi_]);
                            float ig = sigm(acc[2 * 2 + na][eh * 2 + e] + s_bias[2 * 32 + bi_]);
                            float og = sigm(acc[3 * 2 + na][eh * 2 + e] + s_bias[3 * 32 + bi_]);
                            float cc = tanhf(acc[4 * 2 + na][eh * 2 + e] + s_bias[4 * 32 + bi_]);
                            float clv = (e == 0) ? cl.x : cl.y;
                            float crv = (e == 0) ? cr.x : cr.y;
                            float cn = fl * clv + fr * crv + ig * cc;
                            cv[e] = cn;
                            hv[e] = rnd_tf32(og * tanhf(cn));
                        }
                        *(float2*)(outH + (size_t)row * 256 + c0 + jj) = make_float2(hv[0], hv[1]);
                        *(float2*)(outC + (size_t)row * 256 + c0 + jj) = make_float2(cv[0], cv[1]);
                    }
                }
            }
            __syncthreads();
        }

        // -------- grid-wide barrier --------
        __threadfence();
        __syncthreads();
        if (tid == 0) {
            unsigned arrived = atomicAdd(&g_bar_cnt, 1u);
            if (arrived == SL_GRID - 1) {
                g_bar_cnt = 0;
                __threadfence();
                atomicAdd(&g_bar_gen, 1u);
                gen++;
            } else {
                unsigned cg;
                do {
                    __nanosleep(64);
                    asm volatile("ld.acquire.gpu.u32 %0, [%1];" : "=r"(cg) : "l"(&g_bar_gen) : "memory");
                } while (cg == gen);
                gen = cg;
                __threadfence();
            }
        }
        __syncthreads();

        float* th = inH; inH = outH; outH = th;
        float* tc = inC; inC = outC; outC = tc;
        cur = Mout;
    }

    // classifier on root H (16 nodes) — CTA 0 only
    if (blockIdx.x == 0 && tid < BVAL * 2) {
        int b = tid >> 1, cx = tid & 1;
        float sum = bcls[cx];
        const float* h = inH + (size_t)b * HVAL;
        for (int k = 0; k < HVAL; k++) sum += h[k] * Wcls[k * 2 + cx];
        out[b * 2 + cx] = sum;
    }
}

// ---------------- launch ----------------
extern "C" void kernel_launch(void* const* d_in, const int* in_sizes, int n_in,
                              void* d_out, int out_size) {
    const int*   leaf_ids = (const int*)d_in[0];
    const float* emb  = (const float*)d_in[1];
    const float* Wp   = (const float*)d_in[2];
    const float* bp   = (const float*)d_in[3];
    const float* Wfl  = (const float*)d_in[4];
    const float* bfl  = (const float*)d_in[5];
    const float* Wfr  = (const float*)d_in[6];
    const float* bfr  = (const float*)d_in[7];
    const float* Wi   = (const float*)d_in[8];
    const float* bi   = (const float*)d_in[9];
    const float* Wo   = (const float*)d_in[10];
    const float* bo   = (const float*)d_in[11];
    const float* Wc   = (const float*)d_in[12];
    const float* bc   = (const float*)d_in[13];
    const float* Wcls = (const float*)d_in[14];
    const float* bcls = (const float*)d_in[15];
    float* out = (float*)d_out;

    float *Ah, *Ac, *Bh, *Bc;
    cudaGetSymbolAddress((void**)&Ah, g_bufA_h);
    cudaGetSymbolAddress((void**)&Ac, g_bufA_c);
    cudaGetSymbolAddress((void**)&Bh, g_bufB_h);
    cudaGetSymbolAddress((void**)&Bc, g_bufB_c);

    cudaFuncSetAttribute(level_fused,  cudaFuncAttributeMaxDynamicSharedMemorySize, LV_SMEM);
    cudaFuncSetAttribute(leaf_fused,   cudaFuncAttributeMaxDynamicSharedMemorySize, LF_SMEM);
    cudaFuncSetAttribute(small_levels, cudaFuncAttributeMaxDynamicSharedMemorySize, SL_SMEM);

    pack_weights<<<1024, 256>>>(emb, Wp, Wfl, Wfr, Wi, Wo, Wc, bfl, bfr, bi, bo, bc);

    leaf_fused<<<dim3(NODES0 / 128, 2), 256, LF_SMEM>>>(leaf_ids, bp, Ah, Ac);

    float *inH = Ah, *inC = Ac, *outH = Bh, *outC = Bc;
    int cur = NODES0;
    while (cur > 4096) {
        int Mout = cur >> 1;
        dim3 grid(Mout / 128, 8);
        level_fused<<<grid, 256, LV_SMEM>>>(inH, inC, outH, outC, Mout);
        float* t;
        t = inH; inH = outH; outH = t;
        t = inC; inC = outC; outC = t;
        cur = Mout;
    }

    // cur == 4096 here; persistent kernel does the remaining 8 levels + classifier
    small_levels<<<SL_GRID, 256, SL_SMEM>>>(inH, inC, outH, outC, Wcls, bcls, out);
}